// round 13
// baseline (speedup 1.0000x reference)
#include <cuda_runtime.h>
#include <math.h>
#include <float.h>

#define NB 1024
#define LL 200
#define DD 128
#define KK 3
#define NEG_PAD (-65535.0f)

// Shared layout (floats), 28520 total = 114080 B -> 2 CTAs/SM:
//  cap_s [0,25800)       [200][129] staged tile (scalar access, conflict-free)
//  W4    [25800,26600)   [200][4] softmax weights
//  u4k   [26600,26984)   [3][128]  u atomic-reduce target (k-major)
//  u4p   [26984,27496)   [128][4]  u repacked for float4 broadcast
//  h4    [27496,28008)   [128][4]  high (raw then scaled)
//  g4    [28008,28520)   [128][4]  g
#define SM_FLOATS 28520
#define SMEM_BYTES (SM_FLOATS * 4)

__device__ float g_B[KK * LL];
__device__ float g_delta[3][KK * LL];
__device__ float g_ST[DD * DD];         // ST[e*128+d] = S[d*128+e]

__global__ void routing_init_kernel(const float* __restrict__ Bin,
                                    const float* __restrict__ S)
{
    int idx = blockIdx.x * 256 + threadIdx.x;
    int d = idx >> 7;
    int e = idx & 127;
    g_ST[e * DD + d] = S[idx];
    if (blockIdx.x == 0) {
        for (int t = threadIdx.x; t < KK * LL; t += 256) {
            g_B[t] = Bin[t];
            g_delta[0][t] = 0.f;
            g_delta[1][t] = 0.f;
            g_delta[2][t] = 0.f;
        }
    }
}

__global__ void routing_update_kernel(int it)
{
    int t = threadIdx.x;
    if (t < KK * LL) g_B[t] += g_delta[it][t];
}

__global__ void __launch_bounds__(512, 2)
routing_iter_kernel(const float* __restrict__ cap,
                    const float* __restrict__ S,
                    const void*  __restrict__ seqp,
                    int it,
                    float* __restrict__ out)
{
    extern __shared__ float sm[];
    float* cap_s = sm;
    float* W4    = sm + 25800;
    float* u4k   = sm + 26600;
    float* u4p   = sm + 26984;
    float* h4    = sm + 27496;
    float* g4    = sm + 28008;

    const int b    = blockIdx.x;
    const int tid  = threadIdx.x;
    const int warp = tid >> 5;
    const int lane = tid & 31;

    // ---- sequence length (int32 vs int64 robust) --------------------------
    int n;
    {
        const int* si = (const int*)seqp;
        if (si[1] == 0) n = (int)(((const long long*)seqp)[b]);
        else            n = si[b];
    }

    // ---- softmax (warps 0-2) + zero atomic targets (others) --------------
    if (warp < 3) {
        const int k = warp;
        float v[7];
        float mx = -FLT_MAX;
        #pragma unroll
        for (int i = 0; i < 7; i++) {
            int l = lane + 32 * i;
            float x = -FLT_MAX;
            if (l < LL) x = (l < n) ? g_B[k * LL + l] : NEG_PAD;
            v[i] = x;
            mx = fmaxf(mx, x);
        }
        #pragma unroll
        for (int off = 16; off; off >>= 1)
            mx = fmaxf(mx, __shfl_xor_sync(0xffffffffu, mx, off));
        float s = 0.f;
        #pragma unroll
        for (int i = 0; i < 7; i++) {
            int l = lane + 32 * i;
            float e = (l < LL) ? expf(v[i] - mx) : 0.f;
            v[i] = e;
            s += e;
        }
        #pragma unroll
        for (int off = 16; off; off >>= 1)
            s += __shfl_xor_sync(0xffffffffu, s, off);
        float inv = 1.f / s;
        #pragma unroll
        for (int i = 0; i < 7; i++) {
            int l = lane + 32 * i;
            if (l < LL) {
                W4[l * 4 + k] = v[i] * inv;
                W4[l * 4 + 3] = 0.f;
            }
        }
    } else {
        // zero u4k (384) with warps 3..14; h4+g4 (1024, contiguous) with all spare
        int z = tid - 96;                      // 0..415
        if (z < 384) u4k[z] = 0.f;
        for (int t = tid - 96; t < 1024; t += 416)
            h4[t] = 0.f;                       // h4..g4 contiguous 1024 floats
    }
    __syncthreads();

    // ---- fused sweep: stage cap AND accumulate u partials -----------------
    // warp-iteration covers one row l = warp + 16*itx; lanes own d-quads.
    const float4* capb = (const float4*)(cap + (size_t)b * (LL * DD));
    {
        float4 a0 = make_float4(0.f, 0.f, 0.f, 0.f);
        float4 a1 = a0, a2 = a0;
        #pragma unroll
        for (int bb = 0; bb < 3; bb++) {       // 3 batches x 4 = itx 0..11
            float4 c[4];
            #pragma unroll
            for (int s4 = 0; s4 < 4; s4++)     // batched LDG.128: MLP=4
                c[s4] = capb[tid + 512 * (bb * 4 + s4)];
            #pragma unroll
            for (int s4 = 0; s4 < 4; s4++) {
                int itx = bb * 4 + s4;
                int l = warp + 16 * itx;       // uniform per warp
                float4 wv = *(const float4*)(W4 + l * 4);   // 1 bcast / row
                a0.x = fmaf(wv.x, c[s4].x, a0.x); a0.y = fmaf(wv.x, c[s4].y, a0.y);
                a0.z = fmaf(wv.x, c[s4].z, a0.z); a0.w = fmaf(wv.x, c[s4].w, a0.w);
                a1.x = fmaf(wv.y, c[s4].x, a1.x); a1.y = fmaf(wv.y, c[s4].y, a1.y);
                a1.z = fmaf(wv.y, c[s4].z, a1.z); a1.w = fmaf(wv.y, c[s4].w, a1.w);
                a2.x = fmaf(wv.z, c[s4].x, a2.x); a2.y = fmaf(wv.z, c[s4].y, a2.y);
                a2.z = fmaf(wv.z, c[s4].z, a2.z); a2.w = fmaf(wv.z, c[s4].w, a2.w);
                float* dst = cap_s + l * 129 + 4 * lane;
                dst[0] = c[s4].x; dst[1] = c[s4].y;
                dst[2] = c[s4].z; dst[3] = c[s4].w;
            }
        }
        if (tid < 256) {                       // tail: rows 192..199
            float4 c = capb[tid + 6144];
            int l = 192 + (tid >> 5);
            float4 wv = *(const float4*)(W4 + l * 4);
            a0.x = fmaf(wv.x, c.x, a0.x); a0.y = fmaf(wv.x, c.y, a0.y);
            a0.z = fmaf(wv.x, c.z, a0.z); a0.w = fmaf(wv.x, c.w, a0.w);
            a1.x = fmaf(wv.y, c.x, a1.x); a1.y = fmaf(wv.y, c.y, a1.y);
            a1.z = fmaf(wv.y, c.z, a1.z); a1.w = fmaf(wv.y, c.w, a1.w);
            a2.x = fmaf(wv.z, c.x, a2.x); a2.y = fmaf(wv.z, c.y, a2.y);
            a2.z = fmaf(wv.z, c.z, a2.z); a2.w = fmaf(wv.z, c.w, a2.w);
            float* dst = cap_s + l * 129 + 4 * (tid & 31);
            dst[0] = c.x; dst[1] = c.y; dst[2] = c.z; dst[3] = c.w;
        }
        // atomic-reduce u partials (k-major: addr stride 4 -> 4-way conflicts)
        int dbase = 4 * lane;
        atomicAdd(u4k +           dbase,     a0.x);
        atomicAdd(u4k +           dbase + 1, a0.y);
        atomicAdd(u4k +           dbase + 2, a0.z);
        atomicAdd(u4k +           dbase + 3, a0.w);
        atomicAdd(u4k + 128 +     dbase,     a1.x);
        atomicAdd(u4k + 128 +     dbase + 1, a1.y);
        atomicAdd(u4k + 128 +     dbase + 2, a1.z);
        atomicAdd(u4k + 128 +     dbase + 3, a1.w);
        atomicAdd(u4k + 256 +     dbase,     a2.x);
        atomicAdd(u4k + 256 +     dbase + 1, a2.y);
        atomicAdd(u4k + 256 +     dbase + 2, a2.z);
        atomicAdd(u4k + 256 +     dbase + 3, a2.w);
    }
    __syncthreads();

    // ---- repack u to [d][4] for float4 broadcasts -------------------------
    if (tid < 128) {
        u4p[tid * 4 + 0] = u4k[tid];
        u4p[tid * 4 + 1] = u4k[128 + tid];
        u4p[tid * 4 + 2] = u4k[256 + tid];
        u4p[tid * 4 + 3] = 0.f;
    }
    __syncthreads();

    // ---- hraw[k,e] = sum_d u[k,d]*S[d,e] : (e, d-quarter), atomic reduce --
    {
        const int e = tid & 127;
        const int q = tid >> 7;
        float a0 = 0.f, a1 = 0.f, a2 = 0.f;
        const float* Sp = S + e;
        #pragma unroll 8
        for (int d = q * 32; d < q * 32 + 32; d++) {
            float4 uv = *(const float4*)(u4p + d * 4); // broadcast
            float  s  = Sp[d * DD];                    // coalesced, L1-hot
            a0 = fmaf(uv.x, s, a0);
            a1 = fmaf(uv.y, s, a1);
            a2 = fmaf(uv.z, s, a2);
        }
        atomicAdd(h4 + e * 4 + 0, a0);
        atomicAdd(h4 + e * 4 + 1, a1);
        atomicAdd(h4 + e * 4 + 2, a2);
    }
    __syncthreads();

    // ---- squash over k, write output, rescale h4 in place -----------------
    if (tid < 128) {
        const int e = tid;
        float h0 = h4[e * 4 + 0];
        float h1 = h4[e * 4 + 1];
        float h2 = h4[e * 4 + 2];
        float sq = h0 * h0 + h1 * h1 + h2 * h2;
        float scale = (sq / (1.f + sq)) * rsqrtf(sq + 1e-9f);
        h0 *= scale; h1 *= scale; h2 *= scale;
        float* op = out + (size_t)b * (KK * DD) + e;
        op[0]      = h0;
        op[DD]     = h1;
        op[2 * DD] = h2;
        h4[e * 4 + 0] = h0;
        h4[e * 4 + 1] = h1;
        h4[e * 4 + 2] = h2;
    }
    __syncthreads();

    // ---- g[k,d] = sum_e high[k,e]*ST[e,d] : (d, e-quarter), atomic reduce -
    {
        const int d = tid & 127;
        const int q = tid >> 7;
        float a0 = 0.f, a1 = 0.f, a2 = 0.f;
        const float* STp = g_ST + d;
        #pragma unroll 8
        for (int e = q * 32; e < q * 32 + 32; e++) {
            float4 hv = *(const float4*)(h4 + e * 4);  // broadcast
            float  s  = STp[e * DD];                   // coalesced, L1-hot
            a0 = fmaf(hv.x, s, a0);
            a1 = fmaf(hv.y, s, a1);
            a2 = fmaf(hv.z, s, a2);
        }
        atomicAdd(g4 + d * 4 + 0, a0);
        atomicAdd(g4 + d * 4 + 1, a1);
        atomicAdd(g4 + d * 4 + 2, a2);
    }
    __syncthreads();

    // ---- delta[k,l] += sum_d g[k,d]*cap[l,d] : 2 threads per row ----------
    // Bank stagger (+16 on half 1) keeps even/odd lanes conflict-free.
    {
        const int active = (tid < 400);
        const int l      = active ? (tid >> 1) : 0;
        const int half   = tid & 1;
        float a0 = 0.f, a1 = 0.f, a2 = 0.f;
        const float* cs = cap_s + l * 129;
        #pragma unroll 8
        for (int i = 0; i < 64; i++) {
            int d = half ? (64 + ((i + 16) & 63)) : i;
            float  c  = cs[d];                         // conflict-free
            float4 gv = *(const float4*)(g4 + d * 4);  // 2-addr broadcast
            a0 = fmaf(gv.x, c, a0);
            a1 = fmaf(gv.y, c, a1);
            a2 = fmaf(gv.z, c, a2);
        }
        a0 += __shfl_down_sync(0xffffffffu, a0, 1);
        a1 += __shfl_down_sync(0xffffffffu, a1, 1);
        a2 += __shfl_down_sync(0xffffffffu, a2, 1);
        if (active && half == 0) {
            float* dp = g_delta[it];
            atomicAdd(dp + l,          a0);
            atomicAdd(dp + LL + l,     a1);
            atomicAdd(dp + 2 * LL + l, a2);
        }
    }
}

extern "C" void kernel_launch(void* const* d_in, const int* in_sizes, int n_in,
                              void* d_out, int out_size)
{
    (void)in_sizes; (void)n_in; (void)out_size;
    const float* cap  = (const float*)d_in[0];
    const float* Bin  = (const float*)d_in[1];
    const float* S    = (const float*)d_in[2];
    const void*  seqp = d_in[3];
    float* out = (float*)d_out;

    cudaFuncSetAttribute(routing_iter_kernel,
                         cudaFuncAttributeMaxDynamicSharedMemorySize, SMEM_BYTES);

    routing_init_kernel<<<64, 256>>>(Bin, S);

    routing_iter_kernel<<<NB, 512, SMEM_BYTES>>>(cap, S, seqp, 0, out);
    routing_update_kernel<<<1, 600>>>(0);
    routing_iter_kernel<<<NB, 512, SMEM_BYTES>>>(cap, S, seqp, 1, out);
    routing_update_kernel<<<1, 600>>>(1);
    routing_iter_kernel<<<NB, 512, SMEM_BYTES>>>(cap, S, seqp, 2, out);
}

// round 14
// speedup vs baseline: 1.4684x; 1.4684x over previous
#include <cuda_runtime.h>
#include <math.h>
#include <float.h>

#define NB 1024
#define LL 200
#define DD 128
#define KK 3
#define NEG_PAD (-65535.0f)

// Shared layout (floats), total 28648 = 114592 B -> 2 CTAs/SM:
//  cap_s [0,25800)       [200][129] staged tile (pad 129: staging STS and
//                        delta-pass scalar LDS both conflict-free)
//  W4    [25800,26600)   [200][4] softmax weights; first 512 reused as h4
//  SCR   [26600,28136)   [4][384] reduction slots; first 512 reused as g4
//  u4p   [28136,28648)   [128][4] u packed for float4 broadcast
#define OFF_W4   25800
#define OFF_SCR  26600
#define OFF_U4P  28136
#define SM_FLOATS 28648
#define SMEM_BYTES (SM_FLOATS * 4)

__device__ float g_B[KK * LL];
__device__ float g_delta[3][KK * LL];
__device__ float g_ST[DD * DD];         // ST[e*128+d] = S[d*128+e]

__global__ void routing_init_kernel(const float* __restrict__ Bin,
                                    const float* __restrict__ S)
{
    int idx = blockIdx.x * 256 + threadIdx.x;
    int d = idx >> 7;
    int e = idx & 127;
    g_ST[e * DD + d] = S[idx];
    if (blockIdx.x == 0) {
        for (int t = threadIdx.x; t < KK * LL; t += 256) {
            g_B[t] = Bin[t];
            g_delta[0][t] = 0.f;
            g_delta[1][t] = 0.f;
            g_delta[2][t] = 0.f;
        }
    }
}

__global__ void routing_update_kernel(int it)
{
    int t = threadIdx.x;
    if (t < KK * LL) g_B[t] += g_delta[it][t];
}

__global__ void __launch_bounds__(256, 2)
routing_iter_kernel(const float* __restrict__ cap,
                    const float* __restrict__ S,
                    const void*  __restrict__ seqp,
                    int it,
                    float* __restrict__ out)
{
    extern __shared__ float sm[];
    float* cap_s = sm;
    float* W4    = sm + OFF_W4;
    float* h4    = sm + OFF_W4;        // overlays W4 (dead after sweep)
    float* scr   = sm + OFF_SCR;
    float* g4    = sm + OFF_SCR;       // overlays scratch (after g fold)
    float* u4p   = sm + OFF_U4P;

    const int b    = blockIdx.x;
    const int tid  = threadIdx.x;
    const int warp = tid >> 5;
    const int lane = tid & 31;

    // ---- sequence length (int32 vs int64 robust) --------------------------
    int n;
    {
        const int* si = (const int*)seqp;
        if (si[1] == 0) n = (int)(((const long long*)seqp)[b]);
        else            n = si[b];
    }

    // ---- masked softmax over L for the 3 routing rows (warps 0-2) ---------
    if (warp < 3) {
        const int k = warp;
        float v[7];
        float mx = -FLT_MAX;
        #pragma unroll
        for (int i = 0; i < 7; i++) {
            int l = lane + 32 * i;
            float x = -FLT_MAX;
            if (l < LL) x = (l < n) ? g_B[k * LL + l] : NEG_PAD;
            v[i] = x;
            mx = fmaxf(mx, x);
        }
        #pragma unroll
        for (int off = 16; off; off >>= 1)
            mx = fmaxf(mx, __shfl_xor_sync(0xffffffffu, mx, off));
        float s = 0.f;
        #pragma unroll
        for (int i = 0; i < 7; i++) {
            int l = lane + 32 * i;
            float e = (l < LL) ? expf(v[i] - mx) : 0.f;
            v[i] = e;
            s += e;
        }
        #pragma unroll
        for (int off = 16; off; off >>= 1)
            s += __shfl_xor_sync(0xffffffffu, s, off);
        float inv = 1.f / s;
        #pragma unroll
        for (int i = 0; i < 7; i++) {
            int l = lane + 32 * i;
            if (l < LL) {
                W4[l * 4 + k] = v[i] * inv;
                W4[l * 4 + 3] = 0.f;       // .w lane of the broadcast
            }
        }
    }
    __syncthreads();

    // ---- fused sweep: stage cap AND accumulate u partials -----------------
    // warp-iteration covers one row l = warp + 8*itx; lanes own d-quads.
    const float4* capb = (const float4*)(cap + (size_t)b * (LL * DD));
    float4 a0 = make_float4(0.f, 0.f, 0.f, 0.f);
    float4 a1 = a0, a2 = a0;
    {
        #pragma unroll
        for (int bb = 0; bb < 5; bb++) {
            float4 c[5];
            #pragma unroll
            for (int s5 = 0; s5 < 5; s5++)         // batched LDG.128: MLP=5
                c[s5] = capb[tid + 256 * (bb * 5 + s5)];
            #pragma unroll
            for (int s5 = 0; s5 < 5; s5++) {
                int l = warp + 8 * (bb * 5 + s5);  // uniform per warp
                float4 wv = *(const float4*)(W4 + l * 4);   // 1 bcast / row
                a0.x = fmaf(wv.x, c[s5].x, a0.x); a0.y = fmaf(wv.x, c[s5].y, a0.y);
                a0.z = fmaf(wv.x, c[s5].z, a0.z); a0.w = fmaf(wv.x, c[s5].w, a0.w);
                a1.x = fmaf(wv.y, c[s5].x, a1.x); a1.y = fmaf(wv.y, c[s5].y, a1.y);
                a1.z = fmaf(wv.y, c[s5].z, a1.z); a1.w = fmaf(wv.y, c[s5].w, a1.w);
                a2.x = fmaf(wv.z, c[s5].x, a2.x); a2.y = fmaf(wv.z, c[s5].y, a2.y);
                a2.z = fmaf(wv.z, c[s5].z, a2.z); a2.w = fmaf(wv.z, c[s5].w, a2.w);
                float* dst = cap_s + l * 129 + 4 * lane;    // conflict-free STS
                dst[0] = c[s5].x; dst[1] = c[s5].y;
                dst[2] = c[s5].z; dst[3] = c[s5].w;
            }
        }
    }
    // slot-scratch reduce: warps 0-3 write, warps 4-7 add (exclusive pair slot)
    if (warp < 4) {
        float* rp = scr + warp * 384 + 4 * lane;
        *(float4*)(rp)       = a0;
        *(float4*)(rp + 128) = a1;
        *(float4*)(rp + 256) = a2;
    }
    __syncthreads();
    if (warp >= 4) {
        float* rp = scr + (warp - 4) * 384 + 4 * lane;
        float4 t0 = *(float4*)(rp);
        float4 t1 = *(float4*)(rp + 128);
        float4 t2 = *(float4*)(rp + 256);
        t0.x += a0.x; t0.y += a0.y; t0.z += a0.z; t0.w += a0.w;
        t1.x += a1.x; t1.y += a1.y; t1.z += a1.z; t1.w += a1.w;
        t2.x += a2.x; t2.y += a2.y; t2.z += a2.z; t2.w += a2.w;
        *(float4*)(rp)       = t0;
        *(float4*)(rp + 128) = t1;
        *(float4*)(rp + 256) = t2;
    }
    __syncthreads();
    if (tid < 128) {                       // fold 4 slots -> u4p [d][4]
        float s0 = 0.f, s1 = 0.f, s2 = 0.f;
        #pragma unroll
        for (int s = 0; s < 4; s++) {
            s0 += scr[s * 384 +       tid];
            s1 += scr[s * 384 + 128 + tid];
            s2 += scr[s * 384 + 256 + tid];
        }
        *(float4*)(u4p + tid * 4) = make_float4(s0, s1, s2, 0.f);
    }
    __syncthreads();

    // ---- hraw[k,e] = sum_d u[k,d]*S[d,e] : warp owns 16-d strip, lane=e-quad
    {
        float4 b0 = make_float4(0.f, 0.f, 0.f, 0.f);
        float4 b1 = b0, b2 = b0;
        const int d0 = warp * 16;
        #pragma unroll
        for (int dd = 0; dd < 16; dd++) {
            int d = d0 + dd;
            float4 sv = *(const float4*)(S + d * DD + 4 * lane);  // LDG.128
            float4 uv = *(const float4*)(u4p + d * 4);            // broadcast
            b0.x = fmaf(uv.x, sv.x, b0.x); b0.y = fmaf(uv.x, sv.y, b0.y);
            b0.z = fmaf(uv.x, sv.z, b0.z); b0.w = fmaf(uv.x, sv.w, b0.w);
            b1.x = fmaf(uv.y, sv.x, b1.x); b1.y = fmaf(uv.y, sv.y, b1.y);
            b1.z = fmaf(uv.y, sv.z, b1.z); b1.w = fmaf(uv.y, sv.w, b1.w);
            b2.x = fmaf(uv.z, sv.x, b2.x); b2.y = fmaf(uv.z, sv.y, b2.y);
            b2.z = fmaf(uv.z, sv.z, b2.z); b2.w = fmaf(uv.z, sv.w, b2.w);
        }
        if (warp < 4) {
            float* rp = scr + warp * 384 + 4 * lane;
            *(float4*)(rp)       = b0;
            *(float4*)(rp + 128) = b1;
            *(float4*)(rp + 256) = b2;
        }
        __syncthreads();
        if (warp >= 4) {
            float* rp = scr + (warp - 4) * 384 + 4 * lane;
            float4 t0 = *(float4*)(rp);
            float4 t1 = *(float4*)(rp + 128);
            float4 t2 = *(float4*)(rp + 256);
            t0.x += b0.x; t0.y += b0.y; t0.z += b0.z; t0.w += b0.w;
            t1.x += b1.x; t1.y += b1.y; t1.z += b1.z; t1.w += b1.w;
            t2.x += b2.x; t2.y += b2.y; t2.z += b2.z; t2.w += b2.w;
            *(float4*)(rp)       = t0;
            *(float4*)(rp + 128) = t1;
            *(float4*)(rp + 256) = t2;
        }
        __syncthreads();
        if (tid < 128) {                   // fold -> h4 (overlays dead W4)
            float s0 = 0.f, s1 = 0.f, s2 = 0.f;
            #pragma unroll
            for (int s = 0; s < 4; s++) {
                s0 += scr[s * 384 +       tid];
                s1 += scr[s * 384 + 128 + tid];
                s2 += scr[s * 384 + 256 + tid];
            }
            *(float4*)(h4 + tid * 4) = make_float4(s0, s1, s2, 0.f);
        }
    }
    __syncthreads();

    // ---- squash over k, write output, rescale h4 in place -----------------
    if (tid < 128) {
        const int e = tid;
        float4 hv = *(const float4*)(h4 + e * 4);
        float sq = hv.x * hv.x + hv.y * hv.y + hv.z * hv.z;
        float scale = (sq / (1.f + sq)) * rsqrtf(sq + 1e-9f);
        hv.x *= scale; hv.y *= scale; hv.z *= scale;
        float* op = out + (size_t)b * (KK * DD) + e;
        op[0]      = hv.x;
        op[DD]     = hv.y;
        op[2 * DD] = hv.z;
        *(float4*)(h4 + e * 4) = make_float4(hv.x, hv.y, hv.z, 0.f);
    }
    __syncthreads();

    // ---- g[k,d] = sum_e high[k,e]*ST[e,d] : warp owns 16-e strip, lane=d-quad
    {
        float4 b0 = make_float4(0.f, 0.f, 0.f, 0.f);
        float4 b1 = b0, b2 = b0;
        const int e0 = warp * 16;
        #pragma unroll
        for (int ee = 0; ee < 16; ee++) {
            int e = e0 + ee;
            float4 sv = *(const float4*)(g_ST + e * DD + 4 * lane); // LDG.128
            float4 hv = *(const float4*)(h4 + e * 4);               // broadcast
            b0.x = fmaf(hv.x, sv.x, b0.x); b0.y = fmaf(hv.x, sv.y, b0.y);
            b0.z = fmaf(hv.x, sv.z, b0.z); b0.w = fmaf(hv.x, sv.w, b0.w);
            b1.x = fmaf(hv.y, sv.x, b1.x); b1.y = fmaf(hv.y, sv.y, b1.y);
            b1.z = fmaf(hv.y, sv.z, b1.z); b1.w = fmaf(hv.y, sv.w, b1.w);
            b2.x = fmaf(hv.z, sv.x, b2.x); b2.y = fmaf(hv.z, sv.y, b2.y);
            b2.z = fmaf(hv.z, sv.z, b2.z); b2.w = fmaf(hv.z, sv.w, b2.w);
        }
        if (warp < 4) {
            float* rp = scr + warp * 384 + 4 * lane;
            *(float4*)(rp)       = b0;
            *(float4*)(rp + 128) = b1;
            *(float4*)(rp + 256) = b2;
        }
        __syncthreads();
        if (warp >= 4) {
            float* rp = scr + (warp - 4) * 384 + 4 * lane;
            float4 t0 = *(float4*)(rp);
            float4 t1 = *(float4*)(rp + 128);
            float4 t2 = *(float4*)(rp + 256);
            t0.x += b0.x; t0.y += b0.y; t0.z += b0.z; t0.w += b0.w;
            t1.x += b1.x; t1.y += b1.y; t1.z += b1.z; t1.w += b1.w;
            t2.x += b2.x; t2.y += b2.y; t2.z += b2.z; t2.w += b2.w;
            *(float4*)(rp)       = t0;
            *(float4*)(rp + 128) = t1;
            *(float4*)(rp + 256) = t2;
        }
        __syncthreads();
        // fold into registers, then barrier, THEN write g4 over scratch[0:512]
        float s0 = 0.f, s1 = 0.f, s2 = 0.f;
        if (tid < 128) {
            #pragma unroll
            for (int s = 0; s < 4; s++) {
                s0 += scr[s * 384 +       tid];
                s1 += scr[s * 384 + 128 + tid];
                s2 += scr[s * 384 + 256 + tid];
            }
        }
        __syncthreads();                   // all reads done before overwrite
        if (tid < 128)
            *(float4*)(g4 + tid * 4) = make_float4(s0, s1, s2, 0.f);
    }
    __syncthreads();

    // ---- delta[k,l] += sum_d g[k,d]*cap[l,d] : thread-per-row -------------
    if (tid < LL) {
        const int l = tid;
        float d0 = 0.f, d1 = 0.f, d2 = 0.f;
        const float* cs = cap_s + l * 129;         // (l+d)%32: conflict-free
        #pragma unroll 8
        for (int d = 0; d < 128; d++) {
            float4 gv = *(const float4*)(g4 + d * 4);   // broadcast
            float  c  = cs[d];
            d0 = fmaf(gv.x, c, d0);
            d1 = fmaf(gv.y, c, d1);
            d2 = fmaf(gv.z, c, d2);
        }
        float* dp = g_delta[it];
        atomicAdd(dp + l,          d0);
        atomicAdd(dp + LL + l,     d1);
        atomicAdd(dp + 2 * LL + l, d2);
    }
}

extern "C" void kernel_launch(void* const* d_in, const int* in_sizes, int n_in,
                              void* d_out, int out_size)
{
    (void)in_sizes; (void)n_in; (void)out_size;
    const float* cap  = (const float*)d_in[0];
    const float* Bin  = (const float*)d_in[1];
    const float* S    = (const float*)d_in[2];
    const void*  seqp = d_in[3];
    float* out = (float*)d_out;

    cudaFuncSetAttribute(routing_iter_kernel,
                         cudaFuncAttributeMaxDynamicSharedMemorySize, SMEM_BYTES);

    routing_init_kernel<<<64, 256>>>(Bin, S);

    routing_iter_kernel<<<NB, 256, SMEM_BYTES>>>(cap, S, seqp, 0, out);
    routing_update_kernel<<<1, 600>>>(0);
    routing_iter_kernel<<<NB, 256, SMEM_BYTES>>>(cap, S, seqp, 1, out);
    routing_update_kernel<<<1, 600>>>(1);
    routing_iter_kernel<<<NB, 256, SMEM_BYTES>>>(cap, S, seqp, 2, out);
}

// round 15
// speedup vs baseline: 1.6498x; 1.1235x over previous
#include <cuda_runtime.h>
#include <math.h>
#include <float.h>

#define NB 1024
#define LL 200
#define DD 128
#define KK 3
#define NEG_PAD (-65535.0f)

// Shared layout (floats), total 28576 = 114304 B -> 2 CTAs/SM:
//  cap_t [0,25728)       quad-transposed tile: quad q of row l at
//                        float offset 4*(q*201 + l). 16B-aligned for all l;
//                        staging STS.128 and delta LDS.128 both conflict-free.
//  W4    [25728,26528)   [200][4] softmax weights; first 512 reused as h4
//  SCR   [26528,28064)   [4][384] reduction slots; first 384 reused as gk[3][128]
//  u4p   [28064,28576)   [128][4] u packed for float4 broadcast
#define OFF_W4   25728
#define OFF_SCR  26528
#define OFF_U4P  28064
#define SM_FLOATS 28576
#define SMEM_BYTES (SM_FLOATS * 4)

__device__ float g_B[KK * LL];
__device__ float g_delta[3][KK * LL];
__device__ float g_ST[DD * DD];         // ST[e*128+d] = S[d*128+e]

__global__ void routing_init_kernel(const float* __restrict__ Bin,
                                    const float* __restrict__ S)
{
    int idx = blockIdx.x * 256 + threadIdx.x;
    int d = idx >> 7;
    int e = idx & 127;
    g_ST[e * DD + d] = S[idx];
    if (blockIdx.x == 0) {
        for (int t = threadIdx.x; t < KK * LL; t += 256) {
            g_B[t] = Bin[t];
            g_delta[0][t] = 0.f;
            g_delta[1][t] = 0.f;
            g_delta[2][t] = 0.f;
        }
    }
}

__global__ void routing_update_kernel(int it)
{
    int t = threadIdx.x;
    if (t < KK * LL) g_B[t] += g_delta[it][t];
}

__global__ void __launch_bounds__(256, 2)
routing_iter_kernel(const float* __restrict__ cap,
                    const float* __restrict__ S,
                    const void*  __restrict__ seqp,
                    int it,
                    float* __restrict__ out)
{
    extern __shared__ float sm[];
    float* cap_t = sm;
    float* W4    = sm + OFF_W4;
    float* h4    = sm + OFF_W4;        // overlays W4 (dead after sweep)
    float* scr   = sm + OFF_SCR;
    float* gk    = sm + OFF_SCR;       // gk[k][128], overlays scratch after g fold
    float* u4p   = sm + OFF_U4P;

    const int b    = blockIdx.x;
    const int tid  = threadIdx.x;
    const int warp = tid >> 5;
    const int lane = tid & 31;

    // ---- sequence length (int32 vs int64 robust) --------------------------
    int n;
    {
        const int* si = (const int*)seqp;
        if (si[1] == 0) n = (int)(((const long long*)seqp)[b]);
        else            n = si[b];
    }

    // ---- masked softmax over L for the 3 routing rows (warps 0-2) ---------
    if (warp < 3) {
        const int k = warp;
        float v[7];
        float mx = -FLT_MAX;
        #pragma unroll
        for (int i = 0; i < 7; i++) {
            int l = lane + 32 * i;
            float x = -FLT_MAX;
            if (l < LL) x = (l < n) ? g_B[k * LL + l] : NEG_PAD;
            v[i] = x;
            mx = fmaxf(mx, x);
        }
        #pragma unroll
        for (int off = 16; off; off >>= 1)
            mx = fmaxf(mx, __shfl_xor_sync(0xffffffffu, mx, off));
        float s = 0.f;
        #pragma unroll
        for (int i = 0; i < 7; i++) {
            int l = lane + 32 * i;
            float e = (l < LL) ? expf(v[i] - mx) : 0.f;
            v[i] = e;
            s += e;
        }
        #pragma unroll
        for (int off = 16; off; off >>= 1)
            s += __shfl_xor_sync(0xffffffffu, s, off);
        float inv = 1.f / s;
        #pragma unroll
        for (int i = 0; i < 7; i++) {
            int l = lane + 32 * i;
            if (l < LL) {
                W4[l * 4 + k] = v[i] * inv;
                W4[l * 4 + 3] = 0.f;       // .w lane of the broadcast
            }
        }
    }
    __syncthreads();

    // ---- fused sweep: stage cap (quad-transposed) AND accumulate u --------
    // warp-iteration covers one row l = warp + 8*itx; lanes own d-quads (q=lane).
    const float4* capb = (const float4*)(cap + (size_t)b * (LL * DD));
    float4 a0 = make_float4(0.f, 0.f, 0.f, 0.f);
    float4 a1 = a0, a2 = a0;
    {
        #pragma unroll
        for (int bb = 0; bb < 5; bb++) {
            float4 c[5];
            #pragma unroll
            for (int s5 = 0; s5 < 5; s5++)         // batched LDG.128: MLP=5
                c[s5] = capb[tid + 256 * (bb * 5 + s5)];
            #pragma unroll
            for (int s5 = 0; s5 < 5; s5++) {
                int l = warp + 8 * (bb * 5 + s5);  // uniform per warp
                float4 wv = *(const float4*)(W4 + l * 4);   // 1 bcast / row
                a0.x = fmaf(wv.x, c[s5].x, a0.x); a0.y = fmaf(wv.x, c[s5].y, a0.y);
                a0.z = fmaf(wv.x, c[s5].z, a0.z); a0.w = fmaf(wv.x, c[s5].w, a0.w);
                a1.x = fmaf(wv.y, c[s5].x, a1.x); a1.y = fmaf(wv.y, c[s5].y, a1.y);
                a1.z = fmaf(wv.y, c[s5].z, a1.z); a1.w = fmaf(wv.y, c[s5].w, a1.w);
                a2.x = fmaf(wv.z, c[s5].x, a2.x); a2.y = fmaf(wv.z, c[s5].y, a2.y);
                a2.z = fmaf(wv.z, c[s5].z, a2.z); a2.w = fmaf(wv.z, c[s5].w, a2.w);
                // quad-transposed store: one STS.128, conflict-free
                *(float4*)(cap_t + 4 * (lane * 201 + l)) = c[s5];
            }
        }
    }
    // slot-scratch reduce: warps 0-3 write, warps 4-7 add (exclusive pair slot)
    if (warp < 4) {
        float* rp = scr + warp * 384 + 4 * lane;
        *(float4*)(rp)       = a0;
        *(float4*)(rp + 128) = a1;
        *(float4*)(rp + 256) = a2;
    }
    __syncthreads();
    if (warp >= 4) {
        float* rp = scr + (warp - 4) * 384 + 4 * lane;
        float4 t0 = *(float4*)(rp);
        float4 t1 = *(float4*)(rp + 128);
        float4 t2 = *(float4*)(rp + 256);
        t0.x += a0.x; t0.y += a0.y; t0.z += a0.z; t0.w += a0.w;
        t1.x += a1.x; t1.y += a1.y; t1.z += a1.z; t1.w += a1.w;
        t2.x += a2.x; t2.y += a2.y; t2.z += a2.z; t2.w += a2.w;
        *(float4*)(rp)       = t0;
        *(float4*)(rp + 128) = t1;
        *(float4*)(rp + 256) = t2;
    }
    __syncthreads();
    if (tid < 128) {                       // fold 4 slots -> u4p [d][4]
        float s0 = 0.f, s1 = 0.f, s2 = 0.f;
        #pragma unroll
        for (int s = 0; s < 4; s++) {
            s0 += scr[s * 384 +       tid];
            s1 += scr[s * 384 + 128 + tid];
            s2 += scr[s * 384 + 256 + tid];
        }
        *(float4*)(u4p + tid * 4) = make_float4(s0, s1, s2, 0.f);
    }
    __syncthreads();

    // ---- hraw[k,e] = sum_d u[k,d]*S[d,e] : warp owns 16-d strip, lane=e-quad
    {
        float4 b0 = make_float4(0.f, 0.f, 0.f, 0.f);
        float4 b1 = b0, b2 = b0;
        const int d0 = warp * 16;
        #pragma unroll
        for (int dd = 0; dd < 16; dd++) {
            int d = d0 + dd;
            float4 sv = *(const float4*)(S + d * DD + 4 * lane);  // LDG.128
            float4 uv = *(const float4*)(u4p + d * 4);            // broadcast
            b0.x = fmaf(uv.x, sv.x, b0.x); b0.y = fmaf(uv.x, sv.y, b0.y);
            b0.z = fmaf(uv.x, sv.z, b0.z); b0.w = fmaf(uv.x, sv.w, b0.w);
            b1.x = fmaf(uv.y, sv.x, b1.x); b1.y = fmaf(uv.y, sv.y, b1.y);
            b1.z = fmaf(uv.y, sv.z, b1.z); b1.w = fmaf(uv.y, sv.w, b1.w);
            b2.x = fmaf(uv.z, sv.x, b2.x); b2.y = fmaf(uv.z, sv.y, b2.y);
            b2.z = fmaf(uv.z, sv.z, b2.z); b2.w = fmaf(uv.z, sv.w, b2.w);
        }
        if (warp < 4) {
            float* rp = scr + warp * 384 + 4 * lane;
            *(float4*)(rp)       = b0;
            *(float4*)(rp + 128) = b1;
            *(float4*)(rp + 256) = b2;
        }
        __syncthreads();
        if (warp >= 4) {
            float* rp = scr + (warp - 4) * 384 + 4 * lane;
            float4 t0 = *(float4*)(rp);
            float4 t1 = *(float4*)(rp + 128);
            float4 t2 = *(float4*)(rp + 256);
            t0.x += b0.x; t0.y += b0.y; t0.z += b0.z; t0.w += b0.w;
            t1.x += b1.x; t1.y += b1.y; t1.z += b1.z; t1.w += b1.w;
            t2.x += b2.x; t2.y += b2.y; t2.z += b2.z; t2.w += b2.w;
            *(float4*)(rp)       = t0;
            *(float4*)(rp + 128) = t1;
            *(float4*)(rp + 256) = t2;
        }
        __syncthreads();
        if (tid < 128) {                   // fold -> h4 (overlays dead W4)
            float s0 = 0.f, s1 = 0.f, s2 = 0.f;
            #pragma unroll
            for (int s = 0; s < 4; s++) {
                s0 += scr[s * 384 +       tid];
                s1 += scr[s * 384 + 128 + tid];
                s2 += scr[s * 384 + 256 + tid];
            }
            *(float4*)(h4 + tid * 4) = make_float4(s0, s1, s2, 0.f);
        }
    }
    __syncthreads();

    // ---- squash over k, write output, rescale h4 in place -----------------
    if (tid < 128) {
        const int e = tid;
        float4 hv = *(const float4*)(h4 + e * 4);
        float sq = hv.x * hv.x + hv.y * hv.y + hv.z * hv.z;
        float scale = (sq / (1.f + sq)) * rsqrtf(sq + 1e-9f);
        hv.x *= scale; hv.y *= scale; hv.z *= scale;
        float* op = out + (size_t)b * (KK * DD) + e;
        op[0]      = hv.x;
        op[DD]     = hv.y;
        op[2 * DD] = hv.z;
        *(float4*)(h4 + e * 4) = make_float4(hv.x, hv.y, hv.z, 0.f);
    }
    __syncthreads();

    // ---- g[k,d] = sum_e high[k,e]*ST[e,d] : warp owns 16-e strip, lane=d-quad
    {
        float4 b0 = make_float4(0.f, 0.f, 0.f, 0.f);
        float4 b1 = b0, b2 = b0;
        const int e0 = warp * 16;
        #pragma unroll
        for (int ee = 0; ee < 16; ee++) {
            int e = e0 + ee;
            float4 sv = *(const float4*)(g_ST + e * DD + 4 * lane); // LDG.128
            float4 hv = *(const float4*)(h4 + e * 4);               // broadcast
            b0.x = fmaf(hv.x, sv.x, b0.x); b0.y = fmaf(hv.x, sv.y, b0.y);
            b0.z = fmaf(hv.x, sv.z, b0.z); b0.w = fmaf(hv.x, sv.w, b0.w);
            b1.x = fmaf(hv.y, sv.x, b1.x); b1.y = fmaf(hv.y, sv.y, b1.y);
            b1.z = fmaf(hv.y, sv.z, b1.z); b1.w = fmaf(hv.y, sv.w, b1.w);
            b2.x = fmaf(hv.z, sv.x, b2.x); b2.y = fmaf(hv.z, sv.y, b2.y);
            b2.z = fmaf(hv.z, sv.z, b2.z); b2.w = fmaf(hv.z, sv.w, b2.w);
        }
        if (warp < 4) {
            float* rp = scr + warp * 384 + 4 * lane;
            *(float4*)(rp)       = b0;
            *(float4*)(rp + 128) = b1;
            *(float4*)(rp + 256) = b2;
        }
        __syncthreads();
        if (warp >= 4) {
            float* rp = scr + (warp - 4) * 384 + 4 * lane;
            float4 t0 = *(float4*)(rp);
            float4 t1 = *(float4*)(rp + 128);
            float4 t2 = *(float4*)(rp + 256);
            t0.x += b0.x; t0.y += b0.y; t0.z += b0.z; t0.w += b0.w;
            t1.x += b1.x; t1.y += b1.y; t1.z += b1.z; t1.w += b1.w;
            t2.x += b2.x; t2.y += b2.y; t2.z += b2.z; t2.w += b2.w;
            *(float4*)(rp)       = t0;
            *(float4*)(rp + 128) = t1;
            *(float4*)(rp + 256) = t2;
        }
        __syncthreads();
        // fold into registers, barrier, THEN write gk[3][128] over scratch
        float s0 = 0.f, s1 = 0.f, s2 = 0.f;
        if (tid < 128) {
            #pragma unroll
            for (int s = 0; s < 4; s++) {
                s0 += scr[s * 384 +       tid];
                s1 += scr[s * 384 + 128 + tid];
                s2 += scr[s * 384 + 256 + tid];
            }
        }
        __syncthreads();                   // all reads done before overwrite
        if (tid < 128) {
            gk[tid]       = s0;            // gk[0][d]
            gk[128 + tid] = s1;            // gk[1][d]
            gk[256 + tid] = s2;            // gk[2][d]
        }
    }
    __syncthreads();

    // ---- delta[k,l] += sum_d g[k,d]*cap[l,d] : thread-per-row, quad loads -
    // cap_t LDS.128 conflict-free (lanes=consecutive l); g via 3 k-packed
    // float4 broadcasts per quad (was 4 scalar bcasts per 4 d).
    if (tid < LL) {
        const int l = tid;
        float d0 = 0.f, d1 = 0.f, d2 = 0.f;
        #pragma unroll
        for (int jb = 0; jb < 8; jb++) {           // 8 batches x 4 quads
            float4 c[4];
            #pragma unroll
            for (int u = 0; u < 4; u++)            // batched LDS.128: MLP=4
                c[u] = *(const float4*)(cap_t + 4 * ((jb * 4 + u) * 201 + l));
            #pragma unroll
            for (int u = 0; u < 4; u++) {
                int j = jb * 4 + u;
                float4 q0 = *(const float4*)(gk +       4 * j);  // broadcast
                float4 q1 = *(const float4*)(gk + 128 + 4 * j);  // broadcast
                float4 q2 = *(const float4*)(gk + 256 + 4 * j);  // broadcast
                d0 = fmaf(q0.x, c[u].x, fmaf(q0.y, c[u].y,
                     fmaf(q0.z, c[u].z, fmaf(q0.w, c[u].w, d0))));
                d1 = fmaf(q1.x, c[u].x, fmaf(q1.y, c[u].y,
                     fmaf(q1.z, c[u].z, fmaf(q1.w, c[u].w, d1))));
                d2 = fmaf(q2.x, c[u].x, fmaf(q2.y, c[u].y,
                     fmaf(q2.z, c[u].z, fmaf(q2.w, c[u].w, d2))));
            }
        }
        float* dp = g_delta[it];
        atomicAdd(dp + l,          d0);
        atomicAdd(dp + LL + l,     d1);
        atomicAdd(dp + 2 * LL + l, d2);
    }
}

extern "C" void kernel_launch(void* const* d_in, const int* in_sizes, int n_in,
                              void* d_out, int out_size)
{
    (void)in_sizes; (void)n_in; (void)out_size;
    const float* cap  = (const float*)d_in[0];
    const float* Bin  = (const float*)d_in[1];
    const float* S    = (const float*)d_in[2];
    const void*  seqp = d_in[3];
    float* out = (float*)d_out;

    cudaFuncSetAttribute(routing_iter_kernel,
                         cudaFuncAttributeMaxDynamicSharedMemorySize, SMEM_BYTES);

    routing_init_kernel<<<64, 256>>>(Bin, S);

    routing_iter_kernel<<<NB, 256, SMEM_BYTES>>>(cap, S, seqp, 0, out);
    routing_update_kernel<<<1, 600>>>(0);
    routing_iter_kernel<<<NB, 256, SMEM_BYTES>>>(cap, S, seqp, 1, out);
    routing_update_kernel<<<1, 600>>>(1);
    routing_iter_kernel<<<NB, 256, SMEM_BYTES>>>(cap, S, seqp, 2, out);
}